// round 1
// baseline (speedup 1.0000x reference)
#include <cuda_runtime.h>
#include <math.h>

#define BB    2048
#define NN    62
#define FIN   128
#define HID   512
#define HEADS 8
#define FOUT  64
#define NROWS (BB * NN)   // 126976

// Scratch: node features ping-pong between g_hx and g_h (260 MB each).
__device__ float g_hx[(size_t)NROWS * HID];
__device__ float g_h [(size_t)NROWS * HID];

// ---------------------------------------------------------------------------
// K1: fused BatchNorm (over node dim) + input MLP: g_hx = BN(x) @ W_mlp + b
// Block: 128 threads, 8 rows x 512 cols. Each thread: 8 rows x 4 cols.
// ---------------------------------------------------------------------------
__global__ __launch_bounds__(128) void k1_bn_mlp(
    const float* __restrict__ x,
    const float* __restrict__ gamma, const float* __restrict__ beta,
    const float* __restrict__ mean,  const float* __restrict__ var,
    const float* __restrict__ Wm,    const float* __restrict__ bm)
{
    __shared__ float xs[8][FIN];
    int row0 = blockIdx.x * 8;

    for (int idx = threadIdx.x; idx < 8 * FIN; idx += 128) {
        int r = idx >> 7, k = idx & 127;
        int row = row0 + r;
        int n = row % NN;
        float sc = gamma[n] * rsqrtf(var[n] + 1e-5f);
        xs[r][k] = (x[(size_t)row * FIN + k] - mean[n]) * sc + beta[n];
    }
    __syncthreads();

    int col = threadIdx.x * 4;
    float acc[8][4];
#pragma unroll
    for (int r = 0; r < 8; r++)
#pragma unroll
        for (int c = 0; c < 4; c++) acc[r][c] = 0.f;

#pragma unroll 4
    for (int k = 0; k < FIN; k++) {
        float4 w = *(const float4*)(Wm + (size_t)k * HID + col);
#pragma unroll
        for (int r = 0; r < 8; r++) {
            float xv = xs[r][k];
            acc[r][0] += xv * w.x;
            acc[r][1] += xv * w.y;
            acc[r][2] += xv * w.z;
            acc[r][3] += xv * w.w;
        }
    }

    float4 bv = *(const float4*)(bm + col);
#pragma unroll
    for (int r = 0; r < 8; r++) {
        float4 o = make_float4(acc[r][0] + bv.x, acc[r][1] + bv.y,
                               acc[r][2] + bv.z, acc[r][3] + bv.w);
        *(float4*)&g_hx[(size_t)(row0 + r) * HID + col] = o;
    }
}

// ---------------------------------------------------------------------------
// K2: per-layer all-heads projection: g_h = g_hx @ W_gat[l]  (K = 512)
// Output col = head*64 + d. Block: 128 threads over 16 rows x 512 cols.
// Thread (cx = tid&63, ry = tid>>6): 8 rows x 8 cols, 64 fp32 accumulators.
// ---------------------------------------------------------------------------
__global__ __launch_bounds__(128) void k2_proj(const float* __restrict__ Wl)
{
    __shared__ float xs[16][HID];   // 32 KB
    int row0 = blockIdx.x * 16;

    for (int idx = threadIdx.x; idx < 16 * HID; idx += 128) {
        int r = idx >> 9, k = idx & 511;
        xs[r][k] = g_hx[(size_t)(row0 + r) * HID + k];
    }
    __syncthreads();

    int cx = threadIdx.x & 63;
    int ry = threadIdx.x >> 6;
    int col  = cx * 8;            // 0..504, 8 cols per thread, within one head
    int head = col >> 6;
    int d    = col & 63;
    const float* wb = Wl + (size_t)head * HID * FOUT + d;  // W[k][col] = wb[k*64]

    float acc[8][8];
#pragma unroll
    for (int r = 0; r < 8; r++)
#pragma unroll
        for (int c = 0; c < 8; c++) acc[r][c] = 0.f;

#pragma unroll 2
    for (int k = 0; k < HID; k++) {
        float4 wa = *(const float4*)(wb + (size_t)k * FOUT);
        float4 wc = *(const float4*)(wb + (size_t)k * FOUT + 4);
#pragma unroll
        for (int r = 0; r < 8; r++) {
            float xv = xs[ry * 8 + r][k];
            acc[r][0] += xv * wa.x;
            acc[r][1] += xv * wa.y;
            acc[r][2] += xv * wa.z;
            acc[r][3] += xv * wa.w;
            acc[r][4] += xv * wc.x;
            acc[r][5] += xv * wc.y;
            acc[r][6] += xv * wc.z;
            acc[r][7] += xv * wc.w;
        }
    }

#pragma unroll
    for (int r = 0; r < 8; r++) {
        size_t base = (size_t)(row0 + ry * 8 + r) * HID + col;
        *(float4*)&g_h[base]     = make_float4(acc[r][0], acc[r][1], acc[r][2], acc[r][3]);
        *(float4*)&g_h[base + 4] = make_float4(acc[r][4], acc[r][5], acc[r][6], acc[r][7]);
    }
}

// ---------------------------------------------------------------------------
// K4: per-(batch, head) attention block.
//   f1 = h.a1 (j term), f2 = h.a2 (i term)
//   e[i][j] = leaky(f2[i] + f1[j]) masked by adj[b,i,j]
//   softmax over i (columns), hp[i] = sum_j att[i][j]*h[j], ELU, write g_hx.
// ---------------------------------------------------------------------------
__global__ __launch_bounds__(256) void k4_attn(
    const int* __restrict__ adj, const float* __restrict__ a_l)
{
    __shared__ float hs[NN][FOUT + 1];     // padded: stride 65 kills conflicts
    __shared__ float es[64][NN + 1];       // padded rows for reg-tile overread
    __shared__ float asv[2 * FOUT];
    __shared__ float f1[NN], f2[NN];

    int b    = blockIdx.x;
    int head = blockIdx.y;
    int tid  = threadIdx.x;

    const float* hbase = &g_h[(size_t)b * NN * HID + head * FOUT];
    for (int idx = tid; idx < NN * FOUT; idx += 256) {
        int j = idx >> 6, d = idx & 63;
        hs[j][d] = hbase[(size_t)j * HID + d];
    }
    if (tid < 2 * FOUT) asv[tid] = a_l[head * 2 * FOUT + tid];
    // zero padding rows 62,63 of es (read by reg-tiled aggregation)
    if (tid < 2 * (NN + 1)) es[NN + tid / (NN + 1)][tid % (NN + 1)] = 0.f;
    __syncthreads();

    if (tid < NN) {
        float s1 = 0.f, s2 = 0.f;
#pragma unroll
        for (int d = 0; d < FOUT; d++) {
            float v = hs[tid][d];
            s1 += v * asv[d];
            s2 += v * asv[FOUT + d];
        }
        f1[tid] = s1;
        f2[tid] = s2;
    }
    __syncthreads();

    const int* adjb = adj + (size_t)b * NN * NN;
    for (int idx = tid; idx < NN * NN; idx += 256) {
        int i = idx / NN, j = idx - i * NN;
        float v = f2[i] + f1[j];
        v = v > 0.f ? v : 0.2f * v;          // LeakyReLU(0.2)
        if (adjb[idx] <= 0) v = -9e15f;
        es[i][j] = v;
    }
    __syncthreads();

    // softmax over i (per column j)
    if (tid < NN) {
        int j = tid;
        float m = -3.4e38f;
        for (int i = 0; i < NN; i++) m = fmaxf(m, es[i][j]);
        float s = 0.f;
        for (int i = 0; i < NN; i++) {
            float e = __expf(es[i][j] - m);
            es[i][j] = e;
            s += e;
        }
        float rs = 1.f / s;
        for (int i = 0; i < NN; i++) es[i][j] *= rs;
    }
    __syncthreads();

    // aggregation: thread (d = tid&63, ig = tid>>2bits) does i = ig + 4*ii
    int d  = tid & 63;
    int ig = tid >> 6;   // 0..3
    float acc[16];
#pragma unroll
    for (int ii = 0; ii < 16; ii++) acc[ii] = 0.f;

    for (int j = 0; j < NN; j++) {
        float hv = hs[j][d];
#pragma unroll
        for (int ii = 0; ii < 16; ii++) {
            acc[ii] += es[ig + ii * 4][j] * hv;   // rows >=62 are zeros
        }
    }

    float* outb = &g_hx[(size_t)b * NN * HID + head * FOUT + d];
#pragma unroll
    for (int ii = 0; ii < 16; ii++) {
        int i = ig + ii * 4;
        if (i < NN) {
            float v = acc[ii];
            v = v > 0.f ? v : expm1f(v);          // ELU(alpha=1)
            outb[(size_t)i * HID] = v;
        }
    }
}

// ---------------------------------------------------------------------------
// K5: pooled = sum_n h_x[b,n,:]; logits = pooled @ W_out + b; log_softmax.
// ---------------------------------------------------------------------------
__global__ __launch_bounds__(512) void k5_out(
    const float* __restrict__ Wout, const float* __restrict__ bout,
    float* __restrict__ out)
{
    int b = blockIdx.x, tid = threadIdx.x;
    const float* hb = &g_hx[(size_t)b * NN * HID];
    float s = 0.f;
    for (int n = 0; n < NN; n++) s += hb[(size_t)n * HID + tid];

    __shared__ float red[512];
    __shared__ float lg[3];
    for (int c = 0; c < 3; c++) {
        red[tid] = s * Wout[tid * 3 + c];
        __syncthreads();
        for (int off = 256; off > 0; off >>= 1) {
            if (tid < off) red[tid] += red[tid + off];
            __syncthreads();
        }
        if (tid == 0) lg[c] = red[0] + bout[c];
        __syncthreads();
    }
    if (tid == 0) {
        float m = fmaxf(lg[0], fmaxf(lg[1], lg[2]));
        float sum = expf(lg[0] - m) + expf(lg[1] - m) + expf(lg[2] - m);
        float lse = logf(sum) + m;
        out[b * 3 + 0] = lg[0] - lse;
        out[b * 3 + 1] = lg[1] - lse;
        out[b * 3 + 2] = lg[2] - lse;
    }
}

// ---------------------------------------------------------------------------
extern "C" void kernel_launch(void* const* d_in, const int* in_sizes, int n_in,
                              void* d_out, int out_size)
{
    const float* x     = (const float*)d_in[0];
    const int*   adj   = (const int*)  d_in[1];
    const float* gamma = (const float*)d_in[2];
    const float* beta  = (const float*)d_in[3];
    const float* mean  = (const float*)d_in[4];
    const float* var   = (const float*)d_in[5];
    const float* Wm    = (const float*)d_in[6];
    const float* bm    = (const float*)d_in[7];
    const float* Wg    = (const float*)d_in[8];
    const float* ag    = (const float*)d_in[9];
    const float* Wo    = (const float*)d_in[10];
    const float* bo    = (const float*)d_in[11];
    float* out = (float*)d_out;

    k1_bn_mlp<<<NROWS / 8, 128>>>(x, gamma, beta, mean, var, Wm, bm);

    for (int l = 0; l < 3; l++) {
        k2_proj<<<NROWS / 16, 128>>>(Wg + (size_t)l * HEADS * HID * FOUT);
        k4_attn<<<dim3(BB, HEADS), 256>>>(adj, ag + (size_t)l * HEADS * 2 * FOUT);
    }

    k5_out<<<BB, 512>>>(Wo, bo, out);
}

// round 5
// speedup vs baseline: 1.6456x; 1.6456x over previous
#include <cuda_runtime.h>
#include <math.h>
#include <cstdint>

#define BB    2048
#define NN    62
#define FIN   128
#define HID   512
#define HEADS 8
#define FOUT  64
#define NROWS (BB * NN)   // 126976

// Scratch: features ping-pong between g_hx and g_h; g_Wr = tf32-rounded W_gat.
__device__ float g_hx[(size_t)NROWS * HID];
__device__ float g_h [(size_t)NROWS * HID];
__device__ float g_Wr[(size_t)3 * HEADS * HID * FOUT];

// ===========================================================================
// helpers
// ===========================================================================
__device__ __forceinline__ uint32_t smem_u32(const void* p) {
    uint32_t a;
    asm("{ .reg .u64 t; cvta.to.shared.u64 t, %1; cvt.u32.u64 %0, t; }"
        : "=r"(a) : "l"(p));
    return a;
}
__device__ __forceinline__ float tf32r(float x) {
    uint32_t u;
    asm("cvt.rna.tf32.f32 %0, %1;" : "=r"(u) : "f"(x));
    return __uint_as_float(u);
}
__device__ __forceinline__ void cp_async16(uint32_t dst, const void* src) {
    asm volatile("cp.async.cg.shared.global [%0], [%1], 16;"
                 :: "r"(dst), "l"(src) : "memory");
}
__device__ __forceinline__ void cp_commit() {
    asm volatile("cp.async.commit_group;" ::: "memory");
}
template <int N>
__device__ __forceinline__ void cp_wait() {
    asm volatile("cp.async.wait_group %0;" :: "n"(N) : "memory");
}
__device__ __forceinline__ void mma_tf32(float* c, const uint32_t* a, const uint32_t* b) {
    asm volatile(
        "mma.sync.aligned.m16n8k8.row.col.f32.tf32.tf32.f32 "
        "{%0,%1,%2,%3}, {%4,%5,%6,%7}, {%8,%9}, {%0,%1,%2,%3};"
        : "+f"(c[0]), "+f"(c[1]), "+f"(c[2]), "+f"(c[3])
        : "r"(a[0]), "r"(a[1]), "r"(a[2]), "r"(a[3]), "r"(b[0]), "r"(b[1]));
}

// ===========================================================================
// K0: round W_gat to tf32 (round-to-nearest) once per launch
// ===========================================================================
__global__ void k0_round_w(const float* __restrict__ Wg) {
    int i = blockIdx.x * 1024 + threadIdx.x;
    if (i < 3 * HEADS * HID * FOUT) g_Wr[i] = tf32r(Wg[i]);
}

// ===========================================================================
// K1: fused BatchNorm + input MLP (output rounded to tf32 for K2)
// ===========================================================================
__global__ __launch_bounds__(128) void k1_bn_mlp(
    const float* __restrict__ x,
    const float* __restrict__ gamma, const float* __restrict__ beta,
    const float* __restrict__ mean,  const float* __restrict__ var,
    const float* __restrict__ Wm,    const float* __restrict__ bm)
{
    __shared__ float xs[8][FIN];
    int row0 = blockIdx.x * 8;

    for (int idx = threadIdx.x; idx < 8 * FIN; idx += 128) {
        int r = idx >> 7, k = idx & 127;
        int row = row0 + r;
        int n = row % NN;
        float sc = gamma[n] * rsqrtf(var[n] + 1e-5f);
        xs[r][k] = (x[(size_t)row * FIN + k] - mean[n]) * sc + beta[n];
    }
    __syncthreads();

    int col = threadIdx.x * 4;
    float acc[8][4];
#pragma unroll
    for (int r = 0; r < 8; r++)
#pragma unroll
        for (int c = 0; c < 4; c++) acc[r][c] = 0.f;

#pragma unroll 4
    for (int k = 0; k < FIN; k++) {
        float4 w = *(const float4*)(Wm + (size_t)k * HID + col);
#pragma unroll
        for (int r = 0; r < 8; r++) {
            float xv = xs[r][k];
            acc[r][0] += xv * w.x;
            acc[r][1] += xv * w.y;
            acc[r][2] += xv * w.z;
            acc[r][3] += xv * w.w;
        }
    }

    float4 bv = *(const float4*)(bm + col);
#pragma unroll
    for (int r = 0; r < 8; r++) {
        float4 o = make_float4(tf32r(acc[r][0] + bv.x), tf32r(acc[r][1] + bv.y),
                               tf32r(acc[r][2] + bv.z), tf32r(acc[r][3] + bv.w));
        *(float4*)&g_hx[(size_t)(row0 + r) * HID + col] = o;
    }
}

// ===========================================================================
// K2 (tf32 mma.sync): g_h = g_hx @ W_gat[l]   [126976 x 512] @ [512 x 512]
// CTA 256 thr, tile 128x128. cp.async 4-stage pipeline, KC=32 per stage.
// Takes the LAYER INDEX; weight pointer formed in device code (g_Wr is a
// device symbol — host-side arithmetic on it was Round-3/4's fatal bug).
// ===========================================================================
#define TM 128
#define TN 128
#define KC 32
#define NS (HID / KC)     // 16
#define NBUF 4
#define A_STRIDE 36
#define B_STRIDE 136
#define A_BYTES (TM * A_STRIDE * 4)        // 18432
#define B_BYTES (KC * B_STRIDE * 4)        // 17408
#define STAGE_BYTES (A_BYTES + B_BYTES)    // 35840
#define K2_SMEM (NBUF * STAGE_BYTES)       // 143360

__global__ __launch_bounds__(256, 1) void k2_mma(int layer)
{
    extern __shared__ __align__(16) char smem[];
    const int tid  = threadIdx.x;
    const int lane = tid & 31;
    const int wid  = tid >> 5;
    const int wm   = wid & 3;     // 4 warps along M
    const int wn   = wid >> 2;    // 2 warps along N
    const int n0   = blockIdx.x * TN;     // col tile FAST grid dim (L2 reuse of A)
    const int row0 = blockIdx.y * TM;
    const uint32_t sbase = smem_u32(smem);
    const float* Wl = g_Wr + (size_t)layer * HEADS * HID * FOUT;
    const float* Wb = Wl + (size_t)(n0 >> 6) * HID * FOUT;

    auto issue_stage = [&](int s) {
        const int p = s & (NBUF - 1);
        const float* Ag = g_hx + (size_t)row0 * HID + s * KC;
        const uint32_t Ad = sbase + p * STAGE_BYTES;
#pragma unroll
        for (int i = 0; i < 4; i++) {
            int idx = tid + i * 256;          // 0..1023
            int r = idx >> 3, k4 = idx & 7;
            cp_async16(Ad + r * (A_STRIDE * 4) + k4 * 16,
                       Ag + (size_t)r * HID + k4 * 4);
        }
        const uint32_t Bd = sbase + p * STAGE_BYTES + A_BYTES;
#pragma unroll
        for (int i = 0; i < 4; i++) {
            int idx = tid + i * 256;          // 0..1023
            int k = idx >> 5, n4 = idx & 31;
            int n = n4 * 4;
            const float* sp = Wb + (size_t)(n >> 6) * HID * FOUT
                                 + (size_t)(s * KC + k) * FOUT + (n & 63);
            cp_async16(Bd + k * (B_STRIDE * 4) + n4 * 16, sp);
        }
    };

    float acc[2][8][4];
#pragma unroll
    for (int mt = 0; mt < 2; mt++)
#pragma unroll
        for (int nt = 0; nt < 8; nt++)
#pragma unroll
            for (int q = 0; q < 4; q++) acc[mt][nt][q] = 0.f;

#pragma unroll
    for (int s = 0; s < NBUF - 1; s++) { issue_stage(s); cp_commit(); }

#pragma unroll 1
    for (int s = 0; s < NS; s++) {
        // Tail-aware wait (empty tail groups complete instantly):
        if (s < NS - 2)       cp_wait<2>();
        else if (s == NS - 2) cp_wait<1>();
        else                  cp_wait<0>();
        __syncthreads();
        if (s + NBUF - 1 < NS) issue_stage(s + NBUF - 1);
        cp_commit();   // uniform group accounting

        const float* As = (const float*)(smem + (s & (NBUF - 1)) * STAGE_BYTES);
        const float* Bs = As + TM * A_STRIDE;

#pragma unroll
        for (int ks = 0; ks < KC / 8; ks++) {
            const int kb = ks * 8;
            uint32_t a[2][4], b[8][2];
#pragma unroll
            for (int mt = 0; mt < 2; mt++) {
                int r = wm * 32 + mt * 16 + (lane >> 2);
                int k = kb + (lane & 3);
                a[mt][0] = __float_as_uint(As[r * A_STRIDE + k]);
                a[mt][1] = __float_as_uint(As[(r + 8) * A_STRIDE + k]);
                a[mt][2] = __float_as_uint(As[r * A_STRIDE + k + 4]);
                a[mt][3] = __float_as_uint(As[(r + 8) * A_STRIDE + k + 4]);
            }
#pragma unroll
            for (int nt = 0; nt < 8; nt++) {
                int c = wn * 64 + nt * 8 + (lane >> 2);
                int k = kb + (lane & 3);
                b[nt][0] = __float_as_uint(Bs[k * B_STRIDE + c]);
                b[nt][1] = __float_as_uint(Bs[(k + 4) * B_STRIDE + c]);
            }
#pragma unroll
            for (int mt = 0; mt < 2; mt++)
#pragma unroll
                for (int nt = 0; nt < 8; nt++)
                    mma_tf32(acc[mt][nt], a[mt], b[nt]);
        }
    }

#pragma unroll
    for (int mt = 0; mt < 2; mt++) {
        int r = row0 + wm * 32 + mt * 16 + (lane >> 2);
#pragma unroll
        for (int nt = 0; nt < 8; nt++) {
            int c = n0 + wn * 64 + nt * 8 + 2 * (lane & 3);
            *(float2*)&g_h[(size_t)r * HID + c] =
                make_float2(acc[mt][nt][0], acc[mt][nt][1]);
            *(float2*)&g_h[(size_t)(r + 8) * HID + c] =
                make_float2(acc[mt][nt][2], acc[mt][nt][3]);
        }
    }
}

// ===========================================================================
// K4: per-(batch, head) attention block; f1/f2 + softmax parallel over 256 thr
// ===========================================================================
__global__ __launch_bounds__(256) void k4_attn(
    const int* __restrict__ adj, const float* __restrict__ a_l)
{
    __shared__ float hs[64][FOUT + 1];     // rows 62,63 zeroed
    __shared__ float es[64][NN + 1];       // rows 62,63 zeroed
    __shared__ float asv[2 * FOUT];
    __shared__ float f1[NN], f2[NN];
    __shared__ float pm[4][64], ps[4][64];

    int b    = blockIdx.x;
    int head = blockIdx.y;
    int tid  = threadIdx.x;

    const float* hbase = &g_h[(size_t)b * NN * HID + head * FOUT];
    for (int idx = tid; idx < NN * FOUT; idx += 256) {
        int j = idx >> 6, d = idx & 63;
        hs[j][d] = hbase[(size_t)j * HID + d];
    }
    if (tid < 2 * FOUT) asv[tid] = a_l[head * 2 * FOUT + tid];
    if (tid < 2 * (NN + 1)) es[NN + tid / (NN + 1)][tid % (NN + 1)] = 0.f;
    if (tid < 2 * (FOUT + 1)) hs[NN + tid / (FOUT + 1)][tid % (FOUT + 1)] = 0.f;
    __syncthreads();

    // f1/f2: 4 threads per node (quad), combine via shfl within the quad.
    {
        int node = tid >> 2, t = tid & 3;    // node 0..63 (62,63 read zeros)
        float s1 = 0.f, s2 = 0.f;
#pragma unroll
        for (int dd = 0; dd < 16; dd++) {
            int d = t * 16 + dd;
            float v = hs[node][d];
            s1 += v * asv[d];
            s2 += v * asv[FOUT + d];
        }
        s1 += __shfl_xor_sync(0xffffffffu, s1, 1);
        s1 += __shfl_xor_sync(0xffffffffu, s1, 2);
        s2 += __shfl_xor_sync(0xffffffffu, s2, 1);
        s2 += __shfl_xor_sync(0xffffffffu, s2, 2);
        if (t == 0 && node < NN) { f1[node] = s1; f2[node] = s2; }
    }
    __syncthreads();

    const int* adjb = adj + (size_t)b * NN * NN;
    for (int idx = tid; idx < NN * NN; idx += 256) {
        int i = idx / NN, j = idx - i * NN;
        float v = f2[i] + f1[j];
        v = v > 0.f ? v : 0.2f * v;
        if (adjb[idx] <= 0) v = -9e15f;
        es[i][j] = v;
    }
    __syncthreads();

    // softmax over i (per column j), 4 threads per column
    {
        int j = tid & 63, q = tid >> 6;
        float m = -3.4e38f;
        if (j < NN) {
#pragma unroll
            for (int ii = 0; ii < 16; ii++) {
                int i = q + ii * 4;
                if (i < NN) m = fmaxf(m, es[i][j]);
            }
        }
        pm[q][j] = m;
        __syncthreads();
        float M = fmaxf(fmaxf(pm[0][j], pm[1][j]), fmaxf(pm[2][j], pm[3][j]));
        float s = 0.f;
        if (j < NN) {
#pragma unroll
            for (int ii = 0; ii < 16; ii++) {
                int i = q + ii * 4;
                if (i < NN) {
                    float e = __expf(es[i][j] - M);
                    es[i][j] = e;
                    s += e;
                }
            }
        }
        ps[q][j] = s;
        __syncthreads();
        float rs = 1.f / (ps[0][j] + ps[1][j] + ps[2][j] + ps[3][j]);
        if (j < NN) {
#pragma unroll
            for (int ii = 0; ii < 16; ii++) {
                int i = q + ii * 4;
                if (i < NN) es[i][j] *= rs;
            }
        }
    }
    __syncthreads();

    // aggregation: hp[i][d] = sum_j att[i][j] * h[j][d], then ELU
    int d  = tid & 63;
    int ig = tid >> 6;
    float acc[16];
#pragma unroll
    for (int ii = 0; ii < 16; ii++) acc[ii] = 0.f;

    for (int j = 0; j < NN; j++) {
        float hv = hs[j][d];
#pragma unroll
        for (int ii = 0; ii < 16; ii++) {
            acc[ii] += es[ig + ii * 4][j] * hv;   // pad rows are zeros
        }
    }

    float* outb = &g_hx[(size_t)b * NN * HID + head * FOUT + d];
#pragma unroll
    for (int ii = 0; ii < 16; ii++) {
        int i = ig + ii * 4;
        if (i < NN) {
            float v = acc[ii];
            v = v > 0.f ? v : expm1f(v);
            outb[(size_t)i * HID] = tf32r(v);
        }
    }
}

// ===========================================================================
// K5: pool + output head + log_softmax
// ===========================================================================
__global__ __launch_bounds__(512) void k5_out(
    const float* __restrict__ Wout, const float* __restrict__ bout,
    float* __restrict__ out)
{
    int b = blockIdx.x, tid = threadIdx.x;
    const float* hb = &g_hx[(size_t)b * NN * HID];
    float s = 0.f;
    for (int n = 0; n < NN; n++) s += hb[(size_t)n * HID + tid];

    __shared__ float red[512];
    __shared__ float lg[3];
    for (int c = 0; c < 3; c++) {
        red[tid] = s * Wout[tid * 3 + c];
        __syncthreads();
        for (int off = 256; off > 0; off >>= 1) {
            if (tid < off) red[tid] += red[tid + off];
            __syncthreads();
        }
        if (tid == 0) lg[c] = red[0] + bout[c];
        __syncthreads();
    }
    if (tid == 0) {
        float m = fmaxf(lg[0], fmaxf(lg[1], lg[2]));
        float sum = expf(lg[0] - m) + expf(lg[1] - m) + expf(lg[2] - m);
        float lse = logf(sum) + m;
        out[b * 3 + 0] = lg[0] - lse;
        out[b * 3 + 1] = lg[1] - lse;
        out[b * 3 + 2] = lg[2] - lse;
    }
}

// ===========================================================================
extern "C" void kernel_launch(void* const* d_in, const int* in_sizes, int n_in,
                              void* d_out, int out_size)
{
    const float* x     = (const float*)d_in[0];
    const int*   adj   = (const int*)  d_in[1];
    const float* gamma = (const float*)d_in[2];
    const float* beta  = (const float*)d_in[3];
    const float* mean  = (const float*)d_in[4];
    const float* var   = (const float*)d_in[5];
    const float* Wm    = (const float*)d_in[6];
    const float* bm    = (const float*)d_in[7];
    const float* Wg    = (const float*)d_in[8];
    const float* ag    = (const float*)d_in[9];
    const float* Wo    = (const float*)d_in[10];
    const float* bo    = (const float*)d_in[11];
    float* out = (float*)d_out;

    cudaFuncSetAttribute(k2_mma, cudaFuncAttributeMaxDynamicSharedMemorySize, K2_SMEM);

    k0_round_w<<<(3 * HEADS * HID * FOUT + 1023) / 1024, 1024>>>(Wg);
    k1_bn_mlp<<<NROWS / 8, 128>>>(x, gamma, beta, mean, var, Wm, bm);

    for (int l = 0; l < 3; l++) {
        k2_mma<<<dim3(HID / TN, NROWS / TM), 256, K2_SMEM>>>(l);
        k4_attn<<<dim3(BB, HEADS), 256>>>(adj, ag + (size_t)l * HEADS * 2 * FOUT);
    }

    k5_out<<<BB, 512>>>(Wo, bo, out);
}